// round 1
// baseline (speedup 1.0000x reference)
#include <cuda_runtime.h>

#define NQ   12
#define DIM  4096
#define NL   6
#define TPB  256

// padded smem slot to avoid bank conflicts in the stride-16 pass
#define SLOT(i) ((i) + ((i) >> 4))

struct Gate { float2 m00, m01, m10, m11; };

__device__ __forceinline__ void cmuladd2(float2& n, const float2 m, const float2 v) {
    // n += m * v (complex)
    n.x = fmaf(m.x, v.x, fmaf(-m.y, v.y, n.x));
    n.y = fmaf(m.x, v.y, fmaf( m.y, v.x, n.y));
}

template <int P>
__device__ __forceinline__ void apply_gate(float2 v[16], const Gate G) {
#pragma unroll
    for (int j0 = 0; j0 < 16; ++j0) {
        if (j0 & (1 << P)) continue;
        const int j1 = j0 | (1 << P);
        float2 a = v[j0], b = v[j1];
        float2 n0 = make_float2(0.f, 0.f), n1 = make_float2(0.f, 0.f);
        cmuladd2(n0, G.m00, a); cmuladd2(n0, G.m01, b);
        cmuladd2(n1, G.m10, a); cmuladd2(n1, G.m11, b);
        v[j0] = n0; v[j1] = n1;
    }
}

__global__ void __launch_bounds__(TPB, 2)
quantum_kernel(const float* __restrict__ x,
               const float* __restrict__ weights,
               const float* __restrict__ Wlin,
               const float* __restrict__ bias_p,
               float* __restrict__ out)
{
    __shared__ float2 psi[DIM + (DIM >> 4)];           // padded state, ~34 KB
    __shared__ Gate  gates[NL][NQ];                    // 2.3 KB
    __shared__ unsigned short srcHi[NL][64], srcLo[NL][64];   // CNOT-layer permutation (GF2 split)
    __shared__ float Phi[64], Plo[64], Thi[64], Tlo[64];
    __shared__ float cw[NQ], sw[NQ], Wv[NQ];
    __shared__ float red[TPB / 32];

    const int tid = threadIdx.x;
    const int bidx = blockIdx.x;

    // ---------- Phase 1: per-wire embedding trig, linear weights, gate matrices, CNOT tables ----------
    if (tid < NQ) {
        float h = 0.5f * x[bidx * NQ + tid];
        sincosf(h, &sw[tid], &cw[tid]);
        Wv[tid] = Wlin[tid];
    }
    for (int idx = tid; idx < NL * NQ; idx += TPB) {
        const int l = idx / NQ, w = idx % NQ;
        const float* wp = weights + (l * NQ + w) * 3;
        const float phi = wp[0], theta = wp[1], omega = wp[2];
        float st, ct; sincosf(0.5f * theta, &st, &ct);
        const float a = 0.5f * (phi + omega);
        const float b = 0.5f * (phi - omega);
        float sa, ca, sb, cb;
        sincosf(a, &sa, &ca);
        sincosf(b, &sb, &cb);
        Gate G;
        G.m00 = make_float2( ca * ct, -sa * ct);   // exp(-ia)*ct
        G.m01 = make_float2(-cb * st, -sb * st);   // -exp(+ib)*st
        G.m10 = make_float2( cb * st, -sb * st);   // conj(exp(+ib))*st
        G.m11 = make_float2( ca * ct,  sa * ct);   // conj(exp(-ia))*ct
        gates[l][w] = G;
    }
    for (int idx = tid; idx < NL * 128; idx += TPB) {
        const int l = idx >> 7, k = idx & 127;
        const int r = l % (NQ - 1) + 1;
        unsigned v = (k < 64) ? (unsigned)k : ((unsigned)(k - 64) << 6);
        // src = f_{w=0} ∘ f_{w=1} ∘ ... ∘ f_{w=11}; apply w=11 first
        for (int w = NQ - 1; w >= 0; --w) {
            const int t = (w + r) % NQ;
            v ^= ((v >> (NQ - 1 - w)) & 1u) << (NQ - 1 - t);
        }
        if (k < 64) srcLo[l][k] = (unsigned short)v;
        else        srcHi[l][k - 64] = (unsigned short)v;
    }
    __syncthreads();

    // ---------- Phase 2: product-state init tables & expectation-sign tables ----------
    if (tid < 64) {
        const int j = tid;
        float ph = 1.f, pl = 1.f, th = 0.f, tl = 0.f;
#pragma unroll
        for (int w = 0; w < 6; ++w) {
            // hi covers wires 0..5: wire w -> bit (5-w) of hi
            const int bh = (j >> (5 - w)) & 1;
            ph *= bh ? sw[w] : cw[w];
            th += bh ? -Wv[w] : Wv[w];
            // lo covers wires 6..11: wire (6+w) -> bit (5-w) of lo
            const int bl = (j >> (5 - w)) & 1;
            pl *= bl ? sw[6 + w] : cw[6 + w];
            tl += bl ? -Wv[6 + w] : Wv[6 + w];
        }
        Phi[j] = ph; Plo[j] = pl; Thi[j] = th; Tlo[j] = tl;
    }
    __syncthreads();

    // ---------- Circuit: 6 layers x 3 grouped gate passes; CNOT perm fused into gathers ----------
    float2 v[16];
    for (int l = 0; l < NL; ++l) {
        // ---- Pass A: wires 8..11 live in low 4 index bits; gather applies previous layer's CNOT perm
        if (l == 0) {
#pragma unroll
            for (int j = 0; j < 16; ++j) {
                const int i = (tid << 4) | j;
                v[j] = make_float2(Phi[i >> 6] * Plo[i & 63], 0.f);
            }
        } else {
#pragma unroll
            for (int j = 0; j < 16; ++j) {
                const int i = (tid << 4) | j;
                const int s = srcHi[l - 1][i >> 6] ^ srcLo[l - 1][i & 63];
                v[j] = psi[SLOT(s)];
            }
            __syncthreads();   // scattered reads must complete before overwriting
        }
        {
            apply_gate<3>(v, gates[l][8]);
            apply_gate<2>(v, gates[l][9]);
            apply_gate<1>(v, gates[l][10]);
            apply_gate<0>(v, gates[l][11]);
        }
#pragma unroll
        for (int j = 0; j < 16; ++j) psi[SLOT((tid << 4) | j)] = v[j];
        __syncthreads();

        // ---- Pass B: wires 4..7 (index bits 7..4)
#pragma unroll
        for (int j = 0; j < 16; ++j) {
            const int i = ((tid & 0xF0) << 4) | (j << 4) | (tid & 15);
            v[j] = psi[SLOT(i)];
        }
        apply_gate<3>(v, gates[l][4]);
        apply_gate<2>(v, gates[l][5]);
        apply_gate<1>(v, gates[l][6]);
        apply_gate<0>(v, gates[l][7]);
#pragma unroll
        for (int j = 0; j < 16; ++j) {
            const int i = ((tid & 0xF0) << 4) | (j << 4) | (tid & 15);
            psi[SLOT(i)] = v[j];
        }
        __syncthreads();

        // ---- Pass C: wires 0..3 (index bits 11..8)
#pragma unroll
        for (int j = 0; j < 16; ++j) {
            const int i = (j << 8) | tid;
            v[j] = psi[SLOT(i)];
        }
        apply_gate<3>(v, gates[l][0]);
        apply_gate<2>(v, gates[l][1]);
        apply_gate<1>(v, gates[l][2]);
        apply_gate<0>(v, gates[l][3]);
#pragma unroll
        for (int j = 0; j < 16; ++j) {
            const int i = (j << 8) | tid;
            psi[SLOT(i)] = v[j];
        }
        __syncthreads();
    }

    // ---------- Readout: final CNOT perm fused into gather; probs * signed-weight sum ----------
    float acc = 0.f;
#pragma unroll
    for (int j = 0; j < 16; ++j) {
        const int i = (tid << 4) | j;
        const int s = srcHi[NL - 1][i >> 6] ^ srcLo[NL - 1][i & 63];
        const float2 a = psi[SLOT(s)];
        acc = fmaf(fmaf(a.x, a.x, a.y * a.y), Thi[i >> 6] + Tlo[i & 63], acc);
    }
#pragma unroll
    for (int o = 16; o; o >>= 1) acc += __shfl_xor_sync(0xFFFFFFFFu, acc, o);
    if ((tid & 31) == 0) red[tid >> 5] = acc;
    __syncthreads();
    if (tid == 0) {
        float s = 0.f;
#pragma unroll
        for (int k = 0; k < TPB / 32; ++k) s += red[k];
        out[bidx] = s + bias_p[0];
    }
}

extern "C" void kernel_launch(void* const* d_in, const int* in_sizes, int n_in,
                              void* d_out, int out_size)
{
    const float* x       = (const float*)d_in[0];
    const float* weights = (const float*)d_in[1];
    const float* W       = (const float*)d_in[2];
    const float* b       = (const float*)d_in[3];
    float* out = (float*)d_out;
    quantum_kernel<<<512, TPB>>>(x, weights, W, b, out);
}